// round 12
// baseline (speedup 1.0000x reference)
#include <cuda_runtime.h>
#include <cstdint>

#define N_MACRO       50000
#define D_FEAT        128
#define SEGS_PER_WARP 8
#define UNROLL        8

// ---------------------------------------------------------------------------
// Single fused kernel: gather + segment-mean over sorted segment ids.
//  - warp w owns segments [w*8, w*8+8)
//  - lanes 0..8 find lower_bound(seg_ids, base+lane) via hint+gallop+binary
//    (ids uniform-random => bound[s] ~ s*n/N_MACRO, sigma ~630 entries)
//  - lane owns 4 dims (one LDG.128 per row); 8-row batches keep 8
//    independent LDG.128 in flight
//  - node ids for a batch fetched by ONE 32B coalesced LDG (1 L1tex
//    wavefront per 8 rows) + SHFL broadcast, replacing 8 broadcast LDGs
//    (8 wavefronts) -> per-row wavefront cost drops 5 -> 4.125
// ---------------------------------------------------------------------------
__global__ void __launch_bounds__(128, 10)
sp_pool_kernel(const float* __restrict__ feat,
               const int*   __restrict__ node_ids,
               const int*   __restrict__ seg_ids,
               float*       __restrict__ out,
               int n)
{
    const int warp = (blockIdx.x * blockDim.x + threadIdx.x) >> 5;
    const int lane = threadIdx.x & 31;
    const int seg_base = warp * SEGS_PER_WARP;
    if (seg_base >= N_MACRO) return;

    // ---- hint + gallop + binary lower_bound (lanes 0..8 meaningful) --------
    const int target = seg_base + min(lane, SEGS_PER_WARP);
    int hint = (int)(((long long)target * (long long)n) / (long long)N_MACRO);
    hint = min(hint, n - 1);

    int l, r;
    if (__ldg(&seg_ids[hint]) < target) {
        int base = hint, step = 256;
        while (base + step < n && __ldg(&seg_ids[base + step]) < target) {
            base += step; step <<= 2;
        }
        l = base + 1;
        r = min(base + step, n);
    } else {
        int top = hint, step = 256;
        while (top - step >= 0 && __ldg(&seg_ids[top - step]) >= target) {
            top -= step; step <<= 2;
        }
        l = (top - step >= 0) ? (top - step + 1) : 0;
        r = top;
    }
    while (l < r) {
        int mid = (l + r) >> 1;
        if (__ldg(&seg_ids[mid]) < target) l = mid + 1;
        else                               r = mid;
    }
    // l == lower_bound(target)

    // ---- gather + mean ------------------------------------------------------
    const int doff = lane * 4;

    #pragma unroll 1
    for (int g = 0; g < SEGS_PER_WARP; ++g) {
        const int s0 = __shfl_sync(0xffffffffu, l, g);
        const int s1 = __shfl_sync(0xffffffffu, l, g + 1);
        const int cnt = s1 - s0;

        float4 acc = make_float4(0.f, 0.f, 0.f, 0.f);

        if (cnt > 0) {
            int j = s0;
            // full 8-row batches: 1 coalesced nid wavefront + 8 indep LDG.128
            for (; j + UNROLL <= s1; j += UNROLL) {
                int myn = __ldg(&node_ids[j + (lane & 7)]);   // 32B, 1 wf
                float4 v[UNROLL];
                #pragma unroll
                for (int k = 0; k < UNROLL; ++k) {
                    int nk = __shfl_sync(0xffffffffu, myn, k);
                    v[k] = *reinterpret_cast<const float4*>(
                        feat + (size_t)nk * D_FEAT + doff);
                }
                #pragma unroll
                for (int k = 0; k < UNROLL; ++k) {
                    acc.x += v[k].x; acc.y += v[k].y;
                    acc.z += v[k].z; acc.w += v[k].w;
                }
            }
            // serial tail (<=7 rows; hidden by co-resident warps)
            for (; j < s1; ++j) {
                int nid = __ldg(&node_ids[j]);
                float4 v = *reinterpret_cast<const float4*>(
                    feat + (size_t)nid * D_FEAT + doff);
                acc.x += v.x; acc.y += v.y; acc.z += v.z; acc.w += v.w;
            }
        }

        // mean (empty segment -> 0, matching sums / max(counts, 1))
        const float inv = (cnt > 0) ? (1.0f / (float)cnt) : 0.0f;
        float4 rr = make_float4(acc.x * inv, acc.y * inv,
                                acc.z * inv, acc.w * inv);
        *reinterpret_cast<float4*>(
            out + (size_t)(seg_base + g) * D_FEAT + doff) = rr;
    }
}

// ---------------------------------------------------------------------------
// Launch
// inputs: node_feature f32 [100000*128], batch_node_ids i32 [n],
//         batch_macro_node_ids i32 [n] (sorted), num_macro_nodes (scalar)
// ---------------------------------------------------------------------------
extern "C" void kernel_launch(void* const* d_in, const int* in_sizes, int n_in,
                              void* d_out, int out_size) {
    const float* feat     = (const float*)d_in[0];
    const int*   node_ids = (const int*)d_in[1];
    const int*   seg_ids  = (const int*)d_in[2];
    float*       out      = (float*)d_out;
    const int n = in_sizes[1];

    const int n_warps  = (N_MACRO + SEGS_PER_WARP - 1) / SEGS_PER_WARP; // 6250
    const int n_blocks = (n_warps * 32 + 127) / 128;                    // 1563
    sp_pool_kernel<<<n_blocks, 128>>>(feat, node_ids, seg_ids, out, n);
}

// round 13
// speedup vs baseline: 1.0890x; 1.0890x over previous
#include <cuda_runtime.h>
#include <cstdint>

#define N_MACRO       50000
#define D_FEAT        128
#define SEGS_PER_WARP 8
#define UNROLL        8

// ---------------------------------------------------------------------------
// Single fused kernel: gather + segment-mean over sorted segment ids.
//  - warp w owns segments [w*8, w*8+8)  (halves search count vs SEGS=4)
//  - lanes 0..8 find lower_bound(seg_ids, base+lane) via hint+gallop+binary
//    (ids uniform-random => bound[s] ~ s*n/N_MACRO, sigma ~630 entries)
//  - gather loop is the R11/R6-proven shape, UNCHANGED: lane owns 4 dims
//    (one LDG.128 per row); 8-row batch of independent per-row broadcast
//    nid loads + 8 independent LDG.128; serial tail.
//    (SHFL-broadcast nid fetch rejected: 3x measured regressions - it
//     serializes the batch behind a nid->SHFL->address chain.)
// ---------------------------------------------------------------------------
__global__ void __launch_bounds__(128, 10)
sp_pool_kernel(const float* __restrict__ feat,
               const int*   __restrict__ node_ids,
               const int*   __restrict__ seg_ids,
               float*       __restrict__ out,
               int n)
{
    const int warp = (blockIdx.x * blockDim.x + threadIdx.x) >> 5;
    const int lane = threadIdx.x & 31;
    const int seg_base = warp * SEGS_PER_WARP;
    if (seg_base >= N_MACRO) return;

    // ---- hint + gallop + binary lower_bound (lanes 0..8 meaningful) --------
    const int target = seg_base + min(lane, SEGS_PER_WARP);
    int hint = (int)(((long long)target * (long long)n) / (long long)N_MACRO);
    hint = min(hint, n - 1);

    int l, r;
    if (__ldg(&seg_ids[hint]) < target) {
        int base = hint, step = 256;
        while (base + step < n && __ldg(&seg_ids[base + step]) < target) {
            base += step; step <<= 2;
        }
        l = base + 1;
        r = min(base + step, n);
    } else {
        int top = hint, step = 256;
        while (top - step >= 0 && __ldg(&seg_ids[top - step]) >= target) {
            top -= step; step <<= 2;
        }
        l = (top - step >= 0) ? (top - step + 1) : 0;
        r = top;
    }
    while (l < r) {
        int mid = (l + r) >> 1;
        if (__ldg(&seg_ids[mid]) < target) l = mid + 1;
        else                               r = mid;
    }
    // l == lower_bound(target)

    // ---- gather + mean (loop identical to R11) -----------------------------
    #pragma unroll
    for (int g = 0; g < SEGS_PER_WARP; ++g) {
        const int s0 = __shfl_sync(0xffffffffu, l, g);
        const int s1 = __shfl_sync(0xffffffffu, l, g + 1);
        const int cnt = s1 - s0;

        float4 acc = make_float4(0.f, 0.f, 0.f, 0.f);

        if (cnt > 0) {
            int j = s0;
            // full 8-row batches: 8 independent nid loads + 8 indep LDG.128
            for (; j + UNROLL <= s1; j += UNROLL) {
                int nid[UNROLL];
                #pragma unroll
                for (int k = 0; k < UNROLL; ++k)
                    nid[k] = __ldg(&node_ids[j + k]);
                float4 v[UNROLL];
                #pragma unroll
                for (int k = 0; k < UNROLL; ++k)
                    v[k] = *reinterpret_cast<const float4*>(
                        feat + (size_t)nid[k] * D_FEAT + lane * 4);
                #pragma unroll
                for (int k = 0; k < UNROLL; ++k) {
                    acc.x += v[k].x; acc.y += v[k].y;
                    acc.z += v[k].z; acc.w += v[k].w;
                }
            }
            // serial tail (<=7 rows; hidden by co-resident warps)
            for (; j < s1; ++j) {
                int nid = __ldg(&node_ids[j]);
                float4 v = *reinterpret_cast<const float4*>(
                    feat + (size_t)nid * D_FEAT + lane * 4);
                acc.x += v.x; acc.y += v.y; acc.z += v.z; acc.w += v.w;
            }
        }

        // mean (empty segment -> 0, matching sums / max(counts, 1))
        const float inv = (cnt > 0) ? (1.0f / (float)cnt) : 0.0f;
        float4 rr = make_float4(acc.x * inv, acc.y * inv,
                                acc.z * inv, acc.w * inv);
        *reinterpret_cast<float4*>(
            out + (size_t)(seg_base + g) * D_FEAT + lane * 4) = rr;
    }
}

// ---------------------------------------------------------------------------
// Launch
// inputs: node_feature f32 [100000*128], batch_node_ids i32 [n],
//         batch_macro_node_ids i32 [n] (sorted), num_macro_nodes (scalar)
// ---------------------------------------------------------------------------
extern "C" void kernel_launch(void* const* d_in, const int* in_sizes, int n_in,
                              void* d_out, int out_size) {
    const float* feat     = (const float*)d_in[0];
    const int*   node_ids = (const int*)d_in[1];
    const int*   seg_ids  = (const int*)d_in[2];
    float*       out      = (float*)d_out;
    const int n = in_sizes[1];

    const int n_warps  = (N_MACRO + SEGS_PER_WARP - 1) / SEGS_PER_WARP; // 6250
    const int n_blocks = (n_warps * 32 + 127) / 128;                    // 1563
    sp_pool_kernel<<<n_blocks, 128>>>(feat, node_ids, seg_ids, out, n);
}